// round 3
// baseline (speedup 1.0000x reference)
#include <cuda_runtime.h>
#include <cuda_bf16.h>
#include <math.h>

// Problem constants
#define T_STEPS 512
#define BATCH   128
#define DIN     256
#define HID     256
#define GATES   1024            // 4*HID
#define NCOLS   2048            // both directions stacked
#define MROWS   65536           // T*B
#define OUT_TB_STRIDE 512       // out row stride (2H)
#define OUT_MAIN (T_STEPS*BATCH*OUT_TB_STRIDE)  // 33,554,432

// Scratch: xg for both directions [MROWS x NCOLS] fp32 (536 MB) + cell states
__device__ float g_xg[(size_t)MROWS * NCOLS];
__device__ float g_c[2][BATCH][HID];

// ---------------------------------------------------------------------------
// Phase 1: xg = X @ Wcat^T + (b_ih + b_hh)   (classic 128x128x16 SGEMM)
// gridDim = (16, 512): blockIdx.x = N tile (cols 0..1023 fwd, 1024..2047 bwd)
// ---------------------------------------------------------------------------
__global__ __launch_bounds__(256) void gemm_xg_kernel(
    const float* __restrict__ X,
    const float* __restrict__ Wf, const float* __restrict__ Wb,
    const float* __restrict__ bif, const float* __restrict__ bhf,
    const float* __restrict__ bib, const float* __restrict__ bhb)
{
    const int bn = blockIdx.x;     // 0..15
    const int bm = blockIdx.y;     // 0..511
    const bool fwd = (bn < 8);
    const float* W  = fwd ? (Wf + (size_t)bn * 128 * DIN)
                          : (Wb + (size_t)(bn - 8) * 128 * DIN);
    const float* bi = fwd ? bif : bib;
    const float* bh = fwd ? bhf : bhb;
    const int nloc_base = (fwd ? bn : bn - 8) * 128;

    __shared__ float As[16][132];
    __shared__ float Bs[16][132];

    const int tid = threadIdx.x;
    const int tx = tid & 15, ty = tid >> 4;

    float acc[8][8];
    #pragma unroll
    for (int i = 0; i < 8; i++)
        #pragma unroll
        for (int j = 0; j < 8; j++) acc[i][j] = 0.f;

    const int loadRow = tid >> 2;          // 0..63
    const int loadK4  = (tid & 3) * 4;     // 0,4,8,12
    const float* Abase = X + (size_t)bm * 128 * DIN;

    for (int k0 = 0; k0 < DIN; k0 += 16) {
        #pragma unroll
        for (int r = 0; r < 2; r++) {
            int row = loadRow + r * 64;
            float4 va = *(const float4*)(Abase + (size_t)row * DIN + k0 + loadK4);
            As[loadK4 + 0][row] = va.x; As[loadK4 + 1][row] = va.y;
            As[loadK4 + 2][row] = va.z; As[loadK4 + 3][row] = va.w;
            float4 vb = *(const float4*)(W + (size_t)row * DIN + k0 + loadK4);
            Bs[loadK4 + 0][row] = vb.x; Bs[loadK4 + 1][row] = vb.y;
            Bs[loadK4 + 2][row] = vb.z; Bs[loadK4 + 3][row] = vb.w;
        }
        __syncthreads();
        #pragma unroll
        for (int k = 0; k < 16; k++) {
            float a[8], b[8];
            float4 a0 = *(const float4*)&As[k][ty * 8];
            float4 a1 = *(const float4*)&As[k][ty * 8 + 4];
            float4 b0 = *(const float4*)&Bs[k][tx * 8];
            float4 b1 = *(const float4*)&Bs[k][tx * 8 + 4];
            a[0]=a0.x; a[1]=a0.y; a[2]=a0.z; a[3]=a0.w;
            a[4]=a1.x; a[5]=a1.y; a[6]=a1.z; a[7]=a1.w;
            b[0]=b0.x; b[1]=b0.y; b[2]=b0.z; b[3]=b0.w;
            b[4]=b1.x; b[5]=b1.y; b[6]=b1.z; b[7]=b1.w;
            #pragma unroll
            for (int i = 0; i < 8; i++)
                #pragma unroll
                for (int j = 0; j < 8; j++)
                    acc[i][j] += a[i] * b[j];
        }
        __syncthreads();
    }

    #pragma unroll
    for (int j = 0; j < 8; j++) {
        int nloc = tx * 8 + j;
        float bv = bi[nloc_base + nloc] + bh[nloc_base + nloc];
        int ncol = bn * 128 + nloc;
        #pragma unroll
        for (int i = 0; i < 8; i++) {
            int m = bm * 128 + ty * 8 + i;
            g_xg[(size_t)m * NCOLS + ncol] = acc[i][j] + bv;
        }
    }
}

// ---------------------------------------------------------------------------
// init cell state from c0
// ---------------------------------------------------------------------------
__global__ void init_c_kernel(const float* __restrict__ c0)
{
    int i = blockIdx.x * 256 + threadIdx.x;   // 0 .. 2*128*256-1
    ((float*)g_c)[i] = c0[i];
}

// ---------------------------------------------------------------------------
// One recurrence step (both directions). grid = (64, 2), block = 128.
//   blockIdx.x = j-slice (4 h-columns), blockIdx.y = dir.
// Each thread: 1 j-column, 4 batches (brow, brow+32, +64, +96), 4 gates.
// h_prev is read from `out` of the previous step (or h0), c in-place global.
// ---------------------------------------------------------------------------
__device__ __forceinline__ float sigm(float x) { return 1.f / (1.f + expf(-x)); }

__global__ __launch_bounds__(128) void lstm_step_kernel(
    const float* __restrict__ Whh_f, const float* __restrict__ Whh_b,
    const float* __restrict__ h0, float* __restrict__ out, int step)
{
    const int dir   = blockIdx.y;
    const int slice = blockIdx.x;         // 0..63
    const int j0    = slice * 4;
    const int t     = (dir == 0) ? step : (T_STEPS - 1 - step);
    const int tid   = threadIdx.x;
    const int jl    = tid & 3;            // local j 0..3
    const int brow  = tid >> 2;           // 0..31

    const float* Whh = (dir == 0) ? Whh_f : Whh_b;

    __shared__ float Ws[16][260];         // [g*4+jl][k]
    __shared__ float hs[128][68];         // [b][k within tile]

    // Load 16 W_hh rows (gate cols for this slice), full K=256.
    #pragma unroll
    for (int i = 0; i < 32; i++) {
        int lin = i * 128 + tid;          // 0..4095
        int r = lin >> 8;                 // 0..15
        int k = lin & 255;
        int grow = (r >> 2) * HID + j0 + (r & 3);
        Ws[r][k] = Whh[(size_t)grow * HID + k];
    }

    // h_prev source
    const float* hprev;
    int hstride;
    if (dir == 0) {
        if (step == 0) { hprev = h0;                hstride = HID; }
        else { hprev = out + (size_t)(t - 1) * BATCH * OUT_TB_STRIDE; hstride = OUT_TB_STRIDE; }
    } else {
        if (step == 0) { hprev = h0 + BATCH * HID;  hstride = HID; }
        else { hprev = out + (size_t)(t + 1) * BATCH * OUT_TB_STRIDE + HID; hstride = OUT_TB_STRIDE; }
    }

    float acc[4][4];   // [gate][b-replica]
    #pragma unroll
    for (int g = 0; g < 4; g++)
        #pragma unroll
        for (int r = 0; r < 4; r++) acc[g][r] = 0.f;

    for (int k0 = 0; k0 < HID; k0 += 64) {
        __syncthreads();
        // load h tile [128 x 64]
        #pragma unroll
        for (int i = 0; i < 16; i++) {
            int lin = i * 128 + tid;      // 0..2047
            int b  = lin >> 4;
            int kq = lin & 15;
            float4 v = *(const float4*)(hprev + (size_t)b * hstride + k0 + kq * 4);
            hs[b][kq * 4 + 0] = v.x; hs[b][kq * 4 + 1] = v.y;
            hs[b][kq * 4 + 2] = v.z; hs[b][kq * 4 + 3] = v.w;
        }
        __syncthreads();
        #pragma unroll 8
        for (int kk = 0; kk < 64; kk++) {
            int k = k0 + kk;
            float w0 = Ws[jl][k];
            float w1 = Ws[4 + jl][k];
            float w2 = Ws[8 + jl][k];
            float w3 = Ws[12 + jl][k];
            float hv0 = hs[brow][kk];
            float hv1 = hs[brow + 32][kk];
            float hv2 = hs[brow + 64][kk];
            float hv3 = hs[brow + 96][kk];
            acc[0][0] += w0 * hv0; acc[0][1] += w0 * hv1; acc[0][2] += w0 * hv2; acc[0][3] += w0 * hv3;
            acc[1][0] += w1 * hv0; acc[1][1] += w1 * hv1; acc[1][2] += w1 * hv2; acc[1][3] += w1 * hv3;
            acc[2][0] += w2 * hv0; acc[2][1] += w2 * hv1; acc[2][2] += w2 * hv2; acc[2][3] += w2 * hv3;
            acc[3][0] += w3 * hv0; acc[3][1] += w3 * hv1; acc[3][2] += w3 * hv2; acc[3][3] += w3 * hv3;
        }
    }

    const int jg = j0 + jl;               // global h column
    #pragma unroll
    for (int r = 0; r < 4; r++) {
        int b = brow + 32 * r;
        size_t xgbase = (size_t)(t * BATCH + b) * NCOLS + dir * GATES + jg;
        float Gi = acc[0][r] + g_xg[xgbase];
        float Gf = acc[1][r] + g_xg[xgbase + 256];
        float Gg = acc[2][r] + g_xg[xgbase + 512];
        float Go = acc[3][r] + g_xg[xgbase + 768];
        float c  = g_c[dir][b][jg];
        float cn = sigm(Gf) * c + sigm(Gi) * tanhf(Gg);
        float hn = sigm(Go) * tanhf(cn);
        g_c[dir][b][jg] = cn;
        out[(size_t)t * BATCH * OUT_TB_STRIDE + (size_t)b * OUT_TB_STRIDE + dir * HID + jg] = hn;
    }
}

// ---------------------------------------------------------------------------
// Tail: hf, cf, hb, cb after the main out tensor
// ---------------------------------------------------------------------------
__global__ void finalize_kernel(float* __restrict__ out)
{
    int i = blockIdx.x * 256 + threadIdx.x;   // 0..32767
    int b = i >> 8, j = i & 255;
    float* tail = out + OUT_MAIN;
    tail[i]             = out[(size_t)(T_STEPS - 1) * BATCH * OUT_TB_STRIDE + (size_t)b * OUT_TB_STRIDE + j]; // hf
    tail[32768 + i]     = g_c[0][b][j];                                                                        // cf
    tail[65536 + i]     = out[(size_t)b * OUT_TB_STRIDE + HID + j];                                            // hb
    tail[98304 + i]     = g_c[1][b][j];                                                                        // cb
}

// ---------------------------------------------------------------------------
extern "C" void kernel_launch(void* const* d_in, const int* in_sizes, int n_in,
                              void* d_out, int out_size)
{
    const float* x     = (const float*)d_in[0];
    const float* h0    = (const float*)d_in[1];
    const float* c0    = (const float*)d_in[2];
    const float* Wih_f = (const float*)d_in[3];
    const float* Whh_f = (const float*)d_in[4];
    const float* bih_f = (const float*)d_in[5];
    const float* bhh_f = (const float*)d_in[6];
    const float* Wih_b = (const float*)d_in[7];
    const float* Whh_b = (const float*)d_in[8];
    const float* bih_b = (const float*)d_in[9];
    const float* bhh_b = (const float*)d_in[10];
    float* out = (float*)d_out;

    gemm_xg_kernel<<<dim3(16, 512), 256>>>(x, Wih_f, Wih_b, bih_f, bhh_f, bih_b, bhh_b);
    init_c_kernel<<<256, 256>>>(c0);
    for (int s = 0; s < T_STEPS; s++)
        lstm_step_kernel<<<dim3(64, 2), 128>>>(Whh_f, Whh_b, h0, out, s);
    finalize_kernel<<<128, 256>>>(out);
}

// round 7
// speedup vs baseline: 1.4332x; 1.4332x over previous
#include <cuda_runtime.h>
#include <cuda_bf16.h>
#include <math.h>

// Problem constants
#define T_STEPS 512
#define BATCH   128
#define DIN     256
#define HID     256
#define GATES   1024            // 4*HID
#define NCOLS   2048            // both directions stacked
#define MROWS   65536           // T*B
#define OUT_TB_STRIDE 512       // out row stride (2H)
#define OUT_MAIN (T_STEPS*BATCH*OUT_TB_STRIDE)  // 33,554,432

#define NBLK_DIR 128            // persistent blocks per direction
#define NTHR     128

// Scratch: xg for both directions [MROWS x NCOLS] fp32 (536 MB)
__device__ float g_xg[(size_t)MROWS * NCOLS];
// per-step arrival counters for the device-wide step barrier
__device__ int g_bar[2][T_STEPS];

// ---------------------------------------------------------------------------
// Phase 1: xg = X @ Wcat^T + (b_ih + b_hh)   (classic 128x128x16 SGEMM)
// ---------------------------------------------------------------------------
__global__ __launch_bounds__(256) void gemm_xg_kernel(
    const float* __restrict__ X,
    const float* __restrict__ Wf, const float* __restrict__ Wb,
    const float* __restrict__ bif, const float* __restrict__ bhf,
    const float* __restrict__ bib, const float* __restrict__ bhb)
{
    const int bn = blockIdx.x;     // 0..15
    const int bm = blockIdx.y;     // 0..511
    const bool fwd = (bn < 8);
    const float* W  = fwd ? (Wf + (size_t)bn * 128 * DIN)
                          : (Wb + (size_t)(bn - 8) * 128 * DIN);
    const float* bi = fwd ? bif : bib;
    const float* bh = fwd ? bhf : bhb;
    const int nloc_base = (fwd ? bn : bn - 8) * 128;

    __shared__ float As[16][132];
    __shared__ float Bs[16][132];

    const int tid = threadIdx.x;
    const int tx = tid & 15, ty = tid >> 4;

    float acc[8][8];
    #pragma unroll
    for (int i = 0; i < 8; i++)
        #pragma unroll
        for (int j = 0; j < 8; j++) acc[i][j] = 0.f;

    const int loadRow = tid >> 2;          // 0..63
    const int loadK4  = (tid & 3) * 4;     // 0,4,8,12
    const float* Abase = X + (size_t)bm * 128 * DIN;

    for (int k0 = 0; k0 < DIN; k0 += 16) {
        #pragma unroll
        for (int r = 0; r < 2; r++) {
            int row = loadRow + r * 64;
            float4 va = *(const float4*)(Abase + (size_t)row * DIN + k0 + loadK4);
            As[loadK4 + 0][row] = va.x; As[loadK4 + 1][row] = va.y;
            As[loadK4 + 2][row] = va.z; As[loadK4 + 3][row] = va.w;
            float4 vb = *(const float4*)(W + (size_t)row * DIN + k0 + loadK4);
            Bs[loadK4 + 0][row] = vb.x; Bs[loadK4 + 1][row] = vb.y;
            Bs[loadK4 + 2][row] = vb.z; Bs[loadK4 + 3][row] = vb.w;
        }
        __syncthreads();
        #pragma unroll
        for (int k = 0; k < 16; k++) {
            float a[8], b[8];
            float4 a0 = *(const float4*)&As[k][ty * 8];
            float4 a1 = *(const float4*)&As[k][ty * 8 + 4];
            float4 b0 = *(const float4*)&Bs[k][tx * 8];
            float4 b1 = *(const float4*)&Bs[k][tx * 8 + 4];
            a[0]=a0.x; a[1]=a0.y; a[2]=a0.z; a[3]=a0.w;
            a[4]=a1.x; a[5]=a1.y; a[6]=a1.z; a[7]=a1.w;
            b[0]=b0.x; b[1]=b0.y; b[2]=b0.z; b[3]=b0.w;
            b[4]=b1.x; b[5]=b1.y; b[6]=b1.z; b[7]=b1.w;
            #pragma unroll
            for (int i = 0; i < 8; i++)
                #pragma unroll
                for (int j = 0; j < 8; j++)
                    acc[i][j] += a[i] * b[j];
        }
        __syncthreads();
    }

    #pragma unroll
    for (int j = 0; j < 8; j++) {
        int nloc = tx * 8 + j;
        float bv = bi[nloc_base + nloc] + bh[nloc_base + nloc];
        int ncol = bn * 128 + nloc;
        #pragma unroll
        for (int i = 0; i < 8; i++) {
            int m = bm * 128 + ty * 8 + i;
            g_xg[(size_t)m * NCOLS + ncol] = acc[i][j] + bv;
        }
    }
}

// ---------------------------------------------------------------------------
// zero the step-barrier counters (must run before the persistent kernel)
// ---------------------------------------------------------------------------
__global__ void zero_bar_kernel()
{
    int i = blockIdx.x * 256 + threadIdx.x;   // 0..1023
    ((int*)g_bar)[i] = 0;
}

// ---------------------------------------------------------------------------
// Persistent recurrence kernel.
// grid = 256 blocks (co-resident): blk = dir*128 + bgrp*16 + jgrp
//   dir:  0 fwd / 1 bwd
//   bgrp: 8 groups of 16 batches
//   jgrp: 16 groups of 16 h-columns
// 128 threads: jl = tid&15 (one j), bp = tid>>4 (pair of batches).
// Each thread: 4 gates x 1 j x 2 batches; c-state in registers; W_hh slice
// persistent in SMEM; h slice staged per step; device-wide barrier per step.
// ---------------------------------------------------------------------------
__device__ __forceinline__ float sigm(float x) { return 1.f / (1.f + expf(-x)); }

#define WS_STRIDE 260           // floats per W row (65 float4, odd -> skewed banks)
#define SMEM_FLOATS (64*WS_STRIDE + 16*WS_STRIDE)
#define SMEM_BYTES  (SMEM_FLOATS * 4)

extern "C" __global__ void __launch_bounds__(NTHR, 2) lstm_persist_kernel(
    const float* __restrict__ Whh_f, const float* __restrict__ Whh_b,
    const float* __restrict__ h0, const float* __restrict__ c0,
    float* __restrict__ out)
{
    extern __shared__ float smem[];
    float* Ws = smem;                      // [64][WS_STRIDE]
    float* hs = smem + 64 * WS_STRIDE;     // [16][WS_STRIDE]

    const int blk  = blockIdx.x;
    const int dir  = blk >> 7;
    const int bgrp = (blk >> 4) & 7;
    const int jgrp = blk & 15;
    const int tid  = threadIdx.x;
    const int jl   = tid & 15;
    const int bp   = tid >> 4;             // 0..7
    const int j    = jgrp * 16 + jl;
    const int b0   = bgrp * 16 + bp * 2;
    const int b1   = b0 + 1;

    const float* Whh = dir ? Whh_b : Whh_f;

    // Load W_hh slice once: rows r = g*16+jj  ->  Whh[(g*256 + jgrp*16 + jj)][k]
    for (int i = tid; i < 64 * 64; i += NTHR) {      // float4 granularity
        int r  = i >> 6;                   // 0..63
        int kq = i & 63;
        int g = r >> 4, jj = r & 15;
        float4 v = *(const float4*)(Whh + ((size_t)(g * 256 + jgrp * 16 + jj)) * HID + kq * 4);
        *(float4*)(Ws + r * WS_STRIDE + kq * 4) = v;
    }

    // cell state lives in registers for the whole recurrence
    float cr0 = c0[(size_t)dir * BATCH * HID + (size_t)b0 * HID + j];
    float cr1 = c0[(size_t)dir * BATCH * HID + (size_t)b1 * HID + j];

    __syncthreads();

    for (int s = 0; s < T_STEPS; s++) {
        const int t = dir ? (T_STEPS - 1 - s) : s;

        // ---- wait until all blocks of this dir finished step s-1 ----
        if (s > 0) {
            if (tid == 0) {
                volatile int* p = &g_bar[dir][s - 1];
                while (*p < NBLK_DIR) { }
            }
            __syncthreads();
            __threadfence();   // acquire: invalidate L1 before reading fresh h
        }

        // ---- prefetch this thread's xg gate biases (independent of h) ----
        const float* xgp = g_xg + ((size_t)t * BATCH + b0) * NCOLS + dir * GATES + j;
        float xi0 = xgp[0],        xf0 = xgp[256],        xg0 = xgp[512],        xo0 = xgp[768];
        float xi1 = xgp[NCOLS],    xf1 = xgp[NCOLS+256],  xg1 = xgp[NCOLS+512],  xo1 = xgp[NCOLS+768];

        // ---- stage h_prev slice [16 batches x 256] into SMEM ----
        const float* hp; int hstr;
        if (s == 0) { hp = h0 + (size_t)dir * BATCH * HID; hstr = HID; }
        else {
            int tp = dir ? (t + 1) : (t - 1);
            hp = out + (size_t)tp * BATCH * OUT_TB_STRIDE + dir * HID;
            hstr = OUT_TB_STRIDE;
        }
        for (int i = tid; i < 16 * 64; i += NTHR) {
            int bb = i >> 6, kq = i & 63;
            float4 v = *(const float4*)(hp + (size_t)(bgrp * 16 + bb) * hstr + kq * 4);
            *(float4*)(hs + bb * WS_STRIDE + kq * 4) = v;
        }
        __syncthreads();

        // ---- register-tiled GEMM fragment: 4 gates x 1 j x 2 batches ----
        float acc[4][2];
        #pragma unroll
        for (int g = 0; g < 4; g++) { acc[g][0] = 0.f; acc[g][1] = 0.f; }

        const float4* h0p = (const float4*)(hs + (bp * 2) * WS_STRIDE);
        const float4* h1p = (const float4*)(hs + (bp * 2 + 1) * WS_STRIDE);
        const float4* w0p = (const float4*)(Ws + (0 * 16 + jl) * WS_STRIDE);
        const float4* w1p = (const float4*)(Ws + (1 * 16 + jl) * WS_STRIDE);
        const float4* w2p = (const float4*)(Ws + (2 * 16 + jl) * WS_STRIDE);
        const float4* w3p = (const float4*)(Ws + (3 * 16 + jl) * WS_STRIDE);

        #pragma unroll 8
        for (int kq = 0; kq < 64; kq++) {
            float4 ha = h0p[kq];
            float4 hb = h1p[kq];
            float4 w;
            w = w0p[kq];
            acc[0][0] = fmaf(w.x,ha.x,fmaf(w.y,ha.y,fmaf(w.z,ha.z,fmaf(w.w,ha.w,acc[0][0]))));
            acc[0][1] = fmaf(w.x,hb.x,fmaf(w.y,hb.y,fmaf(w.z,hb.z,fmaf(w.w,hb.w,acc[0][1]))));
            w = w1p[kq];
            acc[1][0] = fmaf(w.x,ha.x,fmaf(w.y,ha.y,fmaf(w.z,ha.z,fmaf(w.w,ha.w,acc[1][0]))));
            acc[1][1] = fmaf(w.x,hb.x,fmaf(w.y,hb.y,fmaf(w.z,hb.z,fmaf(w.w,hb.w,acc[1][1]))));
            w = w2p[kq];
            acc[2][0] = fmaf(w.x,ha.x,fmaf(w.y,ha.y,fmaf(w.z,ha.z,fmaf(w.w,ha.w,acc[2][0]))));
            acc[2][1] = fmaf(w.x,hb.x,fmaf(w.y,hb.y,fmaf(w.z,hb.z,fmaf(w.w,hb.w,acc[2][1]))));
            w = w3p[kq];
            acc[3][0] = fmaf(w.x,ha.x,fmaf(w.y,ha.y,fmaf(w.z,ha.z,fmaf(w.w,ha.w,acc[3][0]))));
            acc[3][1] = fmaf(w.x,hb.x,fmaf(w.y,hb.y,fmaf(w.z,hb.z,fmaf(w.w,hb.w,acc[3][1]))));
        }

        // ---- fused gate math + h/c update ----
        float Gi0 = acc[0][0] + xi0, Gf0 = acc[1][0] + xf0, Gg0 = acc[2][0] + xg0, Go0 = acc[3][0] + xo0;
        float Gi1 = acc[0][1] + xi1, Gf1 = acc[1][1] + xf1, Gg1 = acc[2][1] + xg1, Go1 = acc[3][1] + xo1;

        float cn0 = sigm(Gf0) * cr0 + sigm(Gi0) * tanhf(Gg0);
        float hn0 = sigm(Go0) * tanhf(cn0);
        float cn1 = sigm(Gf1) * cr1 + sigm(Gi1) * tanhf(Gg1);
        float hn1 = sigm(Go1) * tanhf(cn1);
        cr0 = cn0; cr1 = cn1;

        float* orow = out + (size_t)t * BATCH * OUT_TB_STRIDE + dir * HID + j;
        orow[(size_t)b0 * OUT_TB_STRIDE] = hn0;
        orow[(size_t)b1 * OUT_TB_STRIDE] = hn1;

        // final step: also write hT / cT tails
        if (s == T_STEPS - 1) {
            float* tail_h = out + OUT_MAIN + dir * 65536;          // hf or hb
            float* tail_c = tail_h + 32768;                         // cf or cb
            tail_h[b0 * HID + j] = hn0;  tail_h[b1 * HID + j] = hn1;
            tail_c[b0 * HID + j] = cn0;  tail_c[b1 * HID + j] = cn1;
        }

        // ---- publish h for step s ----
        __threadfence();
        __syncthreads();
        if (tid == 0) atomicAdd(&g_bar[dir][s], 1);
    }
}

// ---------------------------------------------------------------------------
extern "C" void kernel_launch(void* const* d_in, const int* in_sizes, int n_in,
                              void* d_out, int out_size)
{
    const float* x     = (const float*)d_in[0];
    const float* h0    = (const float*)d_in[1];
    const float* c0    = (const float*)d_in[2];
    const float* Wih_f = (const float*)d_in[3];
    const float* Whh_f = (const float*)d_in[4];
    const float* bih_f = (const float*)d_in[5];
    const float* bhh_f = (const float*)d_in[6];
    const float* Wih_b = (const float*)d_in[7];
    const float* Whh_b = (const float*)d_in[8];
    const float* bih_b = (const float*)d_in[9];
    const float* bhh_b = (const float*)d_in[10];
    float* out = (float*)d_out;

    cudaFuncSetAttribute(lstm_persist_kernel,
                         cudaFuncAttributeMaxDynamicSharedMemorySize, SMEM_BYTES);

    gemm_xg_kernel<<<dim3(16, 512), 256>>>(x, Wih_f, Wih_b, bih_f, bhh_f, bih_b, bhh_b);
    zero_bar_kernel<<<4, 256>>>();
    lstm_persist_kernel<<<2 * NBLK_DIR, NTHR, SMEM_BYTES>>>(Whh_f, Whh_b, h0, c0, out);
}

// round 8
// speedup vs baseline: 1.4522x; 1.0132x over previous
#include <cuda_runtime.h>
#include <cuda_bf16.h>
#include <math.h>

// Problem constants
#define T_STEPS 512
#define BATCH   128
#define DIN     256
#define HID     256
#define GATES   1024            // 4*HID
#define NCOLS   2048            // both directions stacked
#define MROWS   65536           // T*B
#define OUT_TB_STRIDE 512       // out row stride (2H)
#define OUT_MAIN (T_STEPS*BATCH*OUT_TB_STRIDE)  // 33,554,432

#define NTHR     64             // threads per persistent block
#define GRP_BLKS 16             // blocks per (dir,bgrp) sync group

// Scratch: xg for both directions [MROWS x NCOLS] fp32 (536 MB)
__device__ float g_xg[(size_t)MROWS * NCOLS];
// per-(dir,bgrp,step) arrival counters
__device__ int g_bar[2][8][T_STEPS];

// ---- packed fp32x2 helpers (Blackwell FFMA2 path) -------------------------
#define PACK2(d, lo, hi) \
    asm("mov.b64 %0, {%1, %2};" : "=l"(d) : "f"(lo), "f"(hi))
#define UNPACK2(lo, hi, s) \
    asm("mov.b64 {%0, %1}, %2;" : "=f"(lo), "=f"(hi) : "l"(s))
#define FMA2(d, a, b) \
    asm("fma.rn.f32x2 %0, %1, %2, %0;" : "+l"(d) : "l"(a), "l"(b))

// ---------------------------------------------------------------------------
// Phase 1: xg = X @ Wcat^T + (b_ih + b_hh)   (classic 128x128x16 SGEMM)
// ---------------------------------------------------------------------------
__global__ __launch_bounds__(256) void gemm_xg_kernel(
    const float* __restrict__ X,
    const float* __restrict__ Wf, const float* __restrict__ Wb,
    const float* __restrict__ bif, const float* __restrict__ bhf,
    const float* __restrict__ bib, const float* __restrict__ bhb)
{
    const int bn = blockIdx.x;     // 0..15
    const int bm = blockIdx.y;     // 0..511
    const bool fwd = (bn < 8);
    const float* W  = fwd ? (Wf + (size_t)bn * 128 * DIN)
                          : (Wb + (size_t)(bn - 8) * 128 * DIN);
    const float* bi = fwd ? bif : bib;
    const float* bh = fwd ? bhf : bhb;
    const int nloc_base = (fwd ? bn : bn - 8) * 128;

    __shared__ float As[16][132];
    __shared__ float Bs[16][132];

    const int tid = threadIdx.x;
    const int tx = tid & 15, ty = tid >> 4;

    float acc[8][8];
    #pragma unroll
    for (int i = 0; i < 8; i++)
        #pragma unroll
        for (int j = 0; j < 8; j++) acc[i][j] = 0.f;

    const int loadRow = tid >> 2;          // 0..63
    const int loadK4  = (tid & 3) * 4;     // 0,4,8,12
    const float* Abase = X + (size_t)bm * 128 * DIN;

    for (int k0 = 0; k0 < DIN; k0 += 16) {
        #pragma unroll
        for (int r = 0; r < 2; r++) {
            int row = loadRow + r * 64;
            float4 va = *(const float4*)(Abase + (size_t)row * DIN + k0 + loadK4);
            As[loadK4 + 0][row] = va.x; As[loadK4 + 1][row] = va.y;
            As[loadK4 + 2][row] = va.z; As[loadK4 + 3][row] = va.w;
            float4 vb = *(const float4*)(W + (size_t)row * DIN + k0 + loadK4);
            Bs[loadK4 + 0][row] = vb.x; Bs[loadK4 + 1][row] = vb.y;
            Bs[loadK4 + 2][row] = vb.z; Bs[loadK4 + 3][row] = vb.w;
        }
        __syncthreads();
        #pragma unroll
        for (int k = 0; k < 16; k++) {
            float a[8], b[8];
            float4 a0 = *(const float4*)&As[k][ty * 8];
            float4 a1 = *(const float4*)&As[k][ty * 8 + 4];
            float4 b0 = *(const float4*)&Bs[k][tx * 8];
            float4 b1 = *(const float4*)&Bs[k][tx * 8 + 4];
            a[0]=a0.x; a[1]=a0.y; a[2]=a0.z; a[3]=a0.w;
            a[4]=a1.x; a[5]=a1.y; a[6]=a1.z; a[7]=a1.w;
            b[0]=b0.x; b[1]=b0.y; b[2]=b0.z; b[3]=b0.w;
            b[4]=b1.x; b[5]=b1.y; b[6]=b1.z; b[7]=b1.w;
            #pragma unroll
            for (int i = 0; i < 8; i++)
                #pragma unroll
                for (int j = 0; j < 8; j++)
                    acc[i][j] += a[i] * b[j];
        }
        __syncthreads();
    }

    #pragma unroll
    for (int j = 0; j < 8; j++) {
        int nloc = tx * 8 + j;
        float bv = bi[nloc_base + nloc] + bh[nloc_base + nloc];
        int ncol = bn * 128 + nloc;
        #pragma unroll
        for (int i = 0; i < 8; i++) {
            int m = bm * 128 + ty * 8 + i;
            g_xg[(size_t)m * NCOLS + ncol] = acc[i][j] + bv;
        }
    }
}

// ---------------------------------------------------------------------------
__global__ void zero_bar_kernel()
{
    int i = blockIdx.x * 256 + threadIdx.x;   // 0..8191
    ((int*)g_bar)[i] = 0;
}

// ---------------------------------------------------------------------------
// Persistent recurrence kernel.
// grid = 256 blocks: blk = dir*128 + bgrp*16 + jgrp
//   dir:  0 fwd / 1 bwd
//   bgrp: 8 groups of 16 batches   (sync group = 16 blocks sharing dir,bgrp)
//   jgrp: 16 groups of 16 h-columns
// 64 threads: jl = tid&15 (one j), bp = tid>>4 (quad of batches).
// Thread tile: 4 gates x 1 j x 4 batches, fp32x2-packed accumulators.
// ---------------------------------------------------------------------------
__device__ __forceinline__ float sigm(float x) { return 1.f / (1.f + expf(-x)); }

#define WS_STRIDE 260           // floats per row (65 float4)
#define SMEM_FLOATS (64*WS_STRIDE + 16*WS_STRIDE)
#define SMEM_BYTES  (SMEM_FLOATS * 4)

extern "C" __global__ void __launch_bounds__(NTHR) lstm_persist_kernel(
    const float* __restrict__ Whh_f, const float* __restrict__ Whh_b,
    const float* __restrict__ h0, const float* __restrict__ c0,
    float* __restrict__ out)
{
    extern __shared__ float smem[];
    float* Ws = smem;                      // [64][WS_STRIDE]  rows r=g*16+jl
    float* hs = smem + 64 * WS_STRIDE;     // [16][WS_STRIDE]  rows = local batch

    const int blk  = blockIdx.x;
    const int dir  = blk >> 7;
    const int bgrp = (blk >> 4) & 7;
    const int jgrp = blk & 15;
    const int tid  = threadIdx.x;
    const int jl   = tid & 15;
    const int bp   = tid >> 4;             // 0..3
    const int j    = jgrp * 16 + jl;
    const int b0   = bgrp * 16 + bp * 4;   // 4 consecutive batches

    const float* Whh = dir ? Whh_b : Whh_f;

    // Load W_hh slice once: row r = g*16+jj -> Whh[g*256 + jgrp*16 + jj][k]
    for (int i = tid; i < 64 * 64; i += NTHR) {      // float4 granularity
        int r  = i >> 6;                   // 0..63
        int kq = i & 63;
        int g = r >> 4, jj = r & 15;
        float4 v = *(const float4*)(Whh + ((size_t)(g * 256 + jgrp * 16 + jj)) * HID + kq * 4);
        *(float4*)(Ws + r * WS_STRIDE + kq * 4) = v;
    }

    // cell state in registers for the whole recurrence
    float cr[4];
    #pragma unroll
    for (int c = 0; c < 4; c++)
        cr[c] = c0[(size_t)dir * BATCH * HID + (size_t)(b0 + c) * HID + j];

    __syncthreads();

    const float4* w0p = (const float4*)(Ws + (0 * 16 + jl) * WS_STRIDE);
    const float4* w1p = (const float4*)(Ws + (1 * 16 + jl) * WS_STRIDE);
    const float4* w2p = (const float4*)(Ws + (2 * 16 + jl) * WS_STRIDE);
    const float4* w3p = (const float4*)(Ws + (3 * 16 + jl) * WS_STRIDE);
    const float4* hp0 = (const float4*)(hs + (bp * 4 + 0) * WS_STRIDE);
    const float4* hp1 = (const float4*)(hs + (bp * 4 + 1) * WS_STRIDE);
    const float4* hp2 = (const float4*)(hs + (bp * 4 + 2) * WS_STRIDE);
    const float4* hp3 = (const float4*)(hs + (bp * 4 + 3) * WS_STRIDE);

    for (int s = 0; s < T_STEPS; s++) {
        const int t = dir ? (T_STEPS - 1 - s) : s;

        // ---- prefetch this thread's xg contributions (independent of h) ----
        float xi[4], xf[4], xg[4], xo[4];
        {
            const float* xgp = g_xg + ((size_t)t * BATCH + b0) * NCOLS + dir * GATES + j;
            #pragma unroll
            for (int c = 0; c < 4; c++) {
                xi[c] = xgp[0]; xf[c] = xgp[256]; xg[c] = xgp[512]; xo[c] = xgp[768];
                xgp += NCOLS;
            }
        }

        // ---- wait for the 16 blocks of (dir,bgrp) to finish step s-1 ----
        if (s > 0) {
            if (tid == 0) {
                volatile int* p = &g_bar[dir][bgrp][s - 1];
                while (*p < GRP_BLKS) { }
            }
            __syncthreads();
            // no fence needed: h is staged with __ldcv (L2-coherent loads)
        }

        // ---- stage h_prev slice [16 batches x 256] into SMEM ----
        {
            const float* hp; int hstr;
            if (s == 0) { hp = h0 + (size_t)dir * BATCH * HID; hstr = HID; }
            else {
                int tp = dir ? (t + 1) : (t - 1);
                hp = out + (size_t)tp * BATCH * OUT_TB_STRIDE + dir * HID;
                hstr = OUT_TB_STRIDE;
            }
            #pragma unroll
            for (int i = 0; i < 16; i++) {
                int lin = i * NTHR + tid;      // 0..1023
                int bb = lin >> 6, kq = lin & 63;
                float4 v = __ldcv((const float4*)(hp + (size_t)(bgrp * 16 + bb) * hstr + kq * 4));
                *(float4*)(hs + bb * WS_STRIDE + kq * 4) = v;
            }
        }
        __syncthreads();

        // ---- GEMM fragment: 4 gates x 1 j x 4 batches, fp32x2 packed ----
        unsigned long long acc[4][2];
        #pragma unroll
        for (int g = 0; g < 4; g++) {
            float z = 0.f;
            PACK2(acc[g][0], z, z);
            PACK2(acc[g][1], z, z);
        }

        #pragma unroll 4
        for (int kq = 0; kq < 64; kq++) {
            float4 w0 = w0p[kq], w1 = w1p[kq], w2 = w2p[kq], w3 = w3p[kq];
            float4 ha = hp0[kq], hb = hp1[kq], hc = hp2[kq], hd = hp3[kq];

            #define K_STEP(E)                                                \
            {                                                                \
                unsigned long long hlo, hhi, wp;                             \
                PACK2(hlo, ha.E, hb.E);                                      \
                PACK2(hhi, hc.E, hd.E);                                      \
                PACK2(wp, w0.E, w0.E);                                       \
                FMA2(acc[0][0], wp, hlo); FMA2(acc[0][1], wp, hhi);          \
                PACK2(wp, w1.E, w1.E);                                       \
                FMA2(acc[1][0], wp, hlo); FMA2(acc[1][1], wp, hhi);          \
                PACK2(wp, w2.E, w2.E);                                       \
                FMA2(acc[2][0], wp, hlo); FMA2(acc[2][1], wp, hhi);          \
                PACK2(wp, w3.E, w3.E);                                       \
                FMA2(acc[3][0], wp, hlo); FMA2(acc[3][1], wp, hhi);          \
            }
            K_STEP(x) K_STEP(y) K_STEP(z) K_STEP(w)
            #undef K_STEP
        }

        // ---- unpack, fused gate math, h/c update ----
        float gi[4], gf[4], gg[4], go[4];
        UNPACK2(gi[0], gi[1], acc[0][0]); UNPACK2(gi[2], gi[3], acc[0][1]);
        UNPACK2(gf[0], gf[1], acc[1][0]); UNPACK2(gf[2], gf[3], acc[1][1]);
        UNPACK2(gg[0], gg[1], acc[2][0]); UNPACK2(gg[2], gg[3], acc[2][1]);
        UNPACK2(go[0], go[1], acc[3][0]); UNPACK2(go[2], go[3], acc[3][1]);

        float* orow = out + (size_t)t * BATCH * OUT_TB_STRIDE + dir * HID + j;
        float hn[4], cn[4];
        #pragma unroll
        for (int c = 0; c < 4; c++) {
            float Gi = gi[c] + xi[c], Gf = gf[c] + xf[c];
            float Gg = gg[c] + xg[c], Go = go[c] + xo[c];
            cn[c] = sigm(Gf) * cr[c] + sigm(Gi) * tanhf(Gg);
            hn[c] = sigm(Go) * tanhf(cn[c]);
            cr[c] = cn[c];
            orow[(size_t)(b0 + c) * OUT_TB_STRIDE] = hn[c];
        }

        // final step: also write hT / cT tails
        if (s == T_STEPS - 1) {
            float* tail_h = out + OUT_MAIN + dir * 65536;          // hf or hb
            float* tail_c = tail_h + 32768;                         // cf or cb
            #pragma unroll
            for (int c = 0; c < 4; c++) {
                tail_h[(b0 + c) * HID + j] = hn[c];
                tail_c[(b0 + c) * HID + j] = cn[c];
            }
        }

        // ---- publish h for step s (release: fence then arrive) ----
        __threadfence();
        __syncthreads();
        if (tid == 0) atomicAdd(&g_bar[dir][bgrp][s], 1);
    }
}

// ---------------------------------------------------------------------------
extern "C" void kernel_launch(void* const* d_in, const int* in_sizes, int n_in,
                              void* d_out, int out_size)
{
    const float* x     = (const float*)d_in[0];
    const float* h0    = (const float*)d_in[1];
    const float* c0    = (const float*)d_in[2];
    const float* Wih_f = (const float*)d_in[3];
    const float* Whh_f = (const float*)d_in[4];
    const float* bih_f = (const float*)d_in[5];
    const float* bhh_f = (const float*)d_in[6];
    const float* Wih_b = (const float*)d_in[7];
    const float* Whh_b = (const float*)d_in[8];
    const float* bih_b = (const float*)d_in[9];
    const float* bhh_b = (const float*)d_in[10];
    float* out = (float*)d_out;

    cudaFuncSetAttribute(lstm_persist_kernel,
                         cudaFuncAttributeMaxDynamicSharedMemorySize, SMEM_BYTES);

    gemm_xg_kernel<<<dim3(16, 512), 256>>>(x, Wih_f, Wih_b, bih_f, bhh_f, bih_b, bhh_b);
    zero_bar_kernel<<<32, 256>>>();
    lstm_persist_kernel<<<256, NTHR, SMEM_BYTES>>>(Whh_f, Whh_b, h0, c0, out);
}